// round 16
// baseline (speedup 1.0000x reference)
#include <cuda_runtime.h>
#include <math.h>
#include <cstdint>

#define GATES 256
#define OBS_  20
#define MB    128    // batch per CTA
#define NT    512    // 16 warps
#define NW    16
#define CC    8      // batch cols per warp

typedef unsigned long long ULL;

// ---- SMEM layout (floats) ----
#define OFF_W    0                       // [128][256] swizzled
#define OFF_BIAS (OFF_W + 128*256)       // [256] permuted
#define OFF_WE   (OFF_BIAS + 256)        // [2][64]
#define OFF_BE   (OFF_WE + 128)          // [64]
#define OFF_WFC  (OFF_BE + 64)           // [2][64]
#define OFF_BFC  (OFF_WFC + 128)         // [2]+pad -> 4
#define OFF_X    (OFF_BFC + 4)           // NW * [64][8]
#define OFF_H    (OFF_X + NW*64*CC)      // NW * [64][8]
#define OFF_OBS  (OFF_H + NW*64*CC)      // NW * [40][8]
#define SMEM_FLOATS (OFF_OBS + NW*40*CC)
#define SMEM_BYTES  (SMEM_FLOATS * 4)    // ~219 KB

#define FMA_F32X2(d, a, b, c_) \
    asm("fma.rn.f32x2 %0, %1, %2, %3;" : "=l"(d) : "l"(a), "l"(b), "l"(c_))
#define PACK_DUP(out, v) \
    asm("mov.b64 %0, {%1, %1};" : "=l"(out) : "r"(v))
#define UNPACK2(lo, hi, in) \
    asm("mov.b64 {%0, %1}, %2;" : "=r"(lo), "=r"(hi) : "l"(in))

__device__ __forceinline__ float sigf(float x) {
    return __fdividef(1.0f, 1.0f + __expf(-x));
}
__device__ __forceinline__ float tanh_(float x) {
    float a = fabsf(x);
    float e = __expf(2.0f * a);
    float t = 1.0f - __fdividef(2.0f, e + 1.0f);
    return copysignf(t, x);
}

__global__ void __launch_bounds__(NT, 1)
vanilla_lstm_kernel(const float* __restrict__ obs,
                    const float* __restrict__ W_emb,  const float* __restrict__ b_emb,
                    const float* __restrict__ Wih_e,  const float* __restrict__ Whh_e,
                    const float* __restrict__ bih_e,  const float* __restrict__ bhh_e,
                    const float* __restrict__ Wih_d,  const float* __restrict__ Whh_d,
                    const float* __restrict__ bih_d,  const float* __restrict__ bhh_d,
                    const float* __restrict__ W_fc,   const float* __restrict__ b_fc,
                    float* __restrict__ out, int pred_len)
{
    extern __shared__ float sm[];
    float* sW    = sm + OFF_W;
    float* sBias = sm + OFF_BIAS;
    float* sWe   = sm + OFF_WE;
    float* sBe   = sm + OFF_BE;
    float* sWfc  = sm + OFF_WFC;
    float* sBfc  = sm + OFF_BFC;

    const int tid  = threadIdx.x;
    const int lane = tid & 31;
    const int w    = tid >> 5;
    const int b0   = blockIdx.x * MB;

    // per-warp strips: [64 k rows][8 cols] floats
    float4* xW4 = (float4*)(sm + OFF_X) + w * 128;   // 2 float4 per k row
    float4* hW4 = (float4*)(sm + OFF_H) + w * 128;
    float*  oW  = sm + OFF_OBS + w * 40 * CC;

    // ---- stage small params ----
    if (tid < 128) sWe[tid] = W_emb[(tid & 63) * 2 + (tid >> 6)];
    if (tid < 64)  sBe[tid] = b_emb[tid];
    if (tid < 128) sWfc[tid] = W_fc[tid];
    if (tid < 2)   sBfc[tid] = b_fc[tid];

    // obs: strip[w][r][c], c = b & 7, w = b >> 3
    for (int i = tid; i < MB * 40; i += NT) {
        int b = i / 40, r = i % 40;
        sm[OFF_OBS + (b >> 3) * 40 * CC + r * CC + (b & 7)] =
            obs[(size_t)(b0 + b) * 40 + r];
    }

    // ---- weight staging, lane-swizzled (proven layout) ----
    auto stageW = [&](const float* Wih, const float* Whh,
                      const float* bih, const float* bhh) {
        for (int i = tid; i < GATES * 64; i += NT) {
            int row = i >> 6, k = i & 63;
            int g = row >> 6, rem = row & 63;
            int l = rem >> 1, d = rem & 1;
            int sz = (l >> 2) & 1;
            int phys = (2 * l + ((g >> 1) ^ sz)) * 4 + (g & 1) * 2 + d;
            sW[k * GATES + phys]        = Wih[i];
            sW[(64 + k) * GATES + phys] = Whh[i];
        }
        for (int row = tid; row < GATES; row += NT) {
            int g = row >> 6, rem = row & 63;
            sBias[(rem >> 1) * 8 + g * 2 + (rem & 1)] = bih[row] + bhh[row];
        }
    };
    stageW(Wih_e, Whh_e, bih_e, bhh_e);
    __syncthreads();

    // ---- per-lane hoisted constants ----
    const int swz = (lane >> 2) & 1;
    const char* wAx = (const char*)sW + (2 * lane + swz) * 16;       // g0,g1
    const char* wBx = (const char*)sW + (2 * lane + 1 - swz) * 16;   // g2,g3
    const char* wAh = wAx + 64 * 1024;
    const char* wBh = wBx + 64 * 1024;

    const int e0 = 2 * lane, e1 = 2 * lane + 1;
    float we00 = sWe[e0], we01 = sWe[64 + e0], be0 = sBe[e0];
    float we10 = sWe[e1], we11 = sWe[64 + e1], be1 = sBe[e1];
    float wfc00 = sWfc[e0], wfc01 = sWfc[e1];
    float wfc10 = sWfc[64 + e0], wfc11 = sWfc[64 + e1];
    float bfc0 = sBfc[0], bfc1 = sBfc[1];

    ULL biasv[4];
    #pragma unroll
    for (int g = 0; g < 4; g++)
        biasv[g] = *(const ULL*)(sBias + lane * 8 + g * 2);

    // embed (transient regs, stored immediately to X strip)
    auto embed_store = [&](const float* p0, const float* p1) {
        float va[8], vb[8];
        #pragma unroll
        for (int j = 0; j < 8; j++) {
            va[j] = fmaxf(fmaf(p0[j], we00, fmaf(p1[j], we01, be0)), 0.f);
            vb[j] = fmaxf(fmaf(p0[j], we10, fmaf(p1[j], we11, be1)), 0.f);
        }
        xW4[2 * e0]     = make_float4(va[0], va[1], va[2], va[3]);
        xW4[2 * e0 + 1] = make_float4(va[4], va[5], va[6], va[7]);
        xW4[2 * e1]     = make_float4(vb[0], vb[1], vb[2], vb[3]);
        xW4[2 * e1 + 1] = make_float4(vb[4], vb[5], vb[6], vb[7]);
    };
    auto embed_obs_store = [&](int tt) {
        float p0[8], p1[8];
        *(float4*)(p0)     = *(const float4*)(oW + (2 * tt) * CC);
        *(float4*)(p0 + 4) = *(const float4*)(oW + (2 * tt) * CC + 4);
        *(float4*)(p1)     = *(const float4*)(oW + (2 * tt + 1) * CC);
        *(float4*)(p1 + 4) = *(const float4*)(oW + (2 * tt + 1) * CC + 4);
        embed_store(p0, p1);
    };

    // 64-k GEMM over 8 cols
    auto gemm64 = [&](const float4* src, const char* wA, const char* wB,
                      ULL a[4][8]) {
        #pragma unroll 4
        for (int k = 0; k < 64; k++) {
            float4 xlo = src[2 * k];
            float4 xhi = src[2 * k + 1];
            ULL xq[8];
            PACK_DUP(xq[0], __float_as_uint(xlo.x));
            PACK_DUP(xq[1], __float_as_uint(xlo.y));
            PACK_DUP(xq[2], __float_as_uint(xlo.z));
            PACK_DUP(xq[3], __float_as_uint(xlo.w));
            PACK_DUP(xq[4], __float_as_uint(xhi.x));
            PACK_DUP(xq[5], __float_as_uint(xhi.y));
            PACK_DUP(xq[6], __float_as_uint(xhi.z));
            PACK_DUP(xq[7], __float_as_uint(xhi.w));
            float4 w01 = *(const float4*)(wA + k * 1024);
            float4 w23 = *(const float4*)(wB + k * 1024);
            ULL wq0 = *(ULL*)&w01.x, wq1 = *(ULL*)&w01.z;
            ULL wq2 = *(ULL*)&w23.x, wq3 = *(ULL*)&w23.z;
            #pragma unroll
            for (int b = 0; b < 8; b++) {
                FMA_F32X2(a[0][b], wq0, xq[b], a[0][b]);
                FMA_F32X2(a[1][b], wq1, xq[b], a[1][b]);
                FMA_F32X2(a[2][b], wq2, xq[b], a[2][b]);
                FMA_F32X2(a[3][b], wq3, xq[b], a[3][b]);
            }
        }
    };

    float c[2][8], hv[2][8];
    #pragma unroll
    for (int d = 0; d < 2; d++)
        #pragma unroll
        for (int b = 0; b < 8; b++) c[d][b] = 0.0f;

    auto epi_col = [&](ULL a[4][8], int b) {
        unsigned i0, i1, f0, f1, g0, g1, o0, o1;
        UNPACK2(i0, i1, a[0][b]);
        UNPACK2(f0, f1, a[1][b]);
        UNPACK2(g0, g1, a[2][b]);
        UNPACK2(o0, o1, a[3][b]);
        {
            float ig = sigf(__uint_as_float(i0));
            float fg = sigf(__uint_as_float(f0));
            float gg = tanh_(__uint_as_float(g0));
            float og = sigf(__uint_as_float(o0));
            float cn = fmaf(fg, c[0][b], ig * gg);
            c[0][b] = cn;
            hv[0][b] = og * tanh_(cn);
        }
        {
            float ig = sigf(__uint_as_float(i1));
            float fg = sigf(__uint_as_float(f1));
            float gg = tanh_(__uint_as_float(g1));
            float og = sigf(__uint_as_float(o1));
            float cn = fmaf(fg, c[1][b], ig * gg);
            c[1][b] = cn;
            hv[1][b] = og * tanh_(cn);
        }
    };
    auto store_h = [&]() {
        hW4[2 * e0]     = make_float4(hv[0][0], hv[0][1], hv[0][2], hv[0][3]);
        hW4[2 * e0 + 1] = make_float4(hv[0][4], hv[0][5], hv[0][6], hv[0][7]);
        hW4[2 * e1]     = make_float4(hv[1][0], hv[1][1], hv[1][2], hv[1][3]);
        hW4[2 * e1 + 1] = make_float4(hv[1][4], hv[1][5], hv[1][6], hv[1][7]);
    };

    const int TOT = OBS_ + pred_len;
    for (int t = 0; t < TOT; t++) {
        if (t == OBS_) {                 // enc -> dec weight swap
            __syncthreads();
            stageW(Wih_d, Whh_d, bih_d, bhh_d);
            __syncthreads();
            #pragma unroll
            for (int g = 0; g < 4; g++)
                biasv[g] = *(const ULL*)(sBias + lane * 8 + g * 2);
        }

        // produce x_t at step start (encoder); decoder x stored at prev iter end.
        // t == OBS_ uses x_19 still in the strip (== first decoder input).
        if (t < OBS_) {
            embed_obs_store(t);
            __syncwarp();
        }

        ULL acc[4][8];
        #pragma unroll
        for (int g = 0; g < 4; g++)
            #pragma unroll
            for (int b = 0; b < 8; b++) acc[g][b] = biasv[g];

        gemm64(xW4, wAx, wBx, acc);
        if (t > 0) gemm64(hW4, wAh, wBh, acc);   // h_0 = 0

        #pragma unroll
        for (int b = 0; b < 8; b++) epi_col(acc, b);

        store_h();

        if (t >= OBS_) {
            // FC: 16-value butterfly over 64 hidden (2 per lane)
            float r[16];
            #pragma unroll
            for (int b = 0; b < 8; b++) {
                r[b]     = fmaf(hv[0][b], wfc00, hv[1][b] * wfc01);
                r[8 + b] = fmaf(hv[0][b], wfc10, hv[1][b] * wfc11);
            }
            #pragma unroll
            for (int off = 16; off >= 1; off >>= 1)
                #pragma unroll
                for (int j = 0; j < 16; j++)
                    r[j] += __shfl_xor_sync(0xffffffffu, r[j], off);
            float p0[8], p1[8];
            #pragma unroll
            for (int b = 0; b < 8; b++) { p0[b] = r[b] + bfc0; p1[b] = r[8 + b] + bfc1; }

            if (lane < 8) {
                float o0v = 0.f, o1v = 0.f;
                #pragma unroll
                for (int b = 0; b < 8; b++)
                    if (lane == b) { o0v = p0[b]; o1v = p1[b]; }
                size_t o = ((size_t)(b0 + w * 8 + lane) * pred_len + (t - OBS_)) * 2;
                *(float2*)(out + o) = make_float2(o0v, o1v);
            }
            if (t < TOT - 1) embed_store(p0, p1);   // x_{t+1} into strip
        }

        __syncwarp();    // strip writes visible before next iteration's reads
    }
}

extern "C" void kernel_launch(void* const* d_in, const int* in_sizes, int n_in,
                              void* d_out, int out_size)
{
    const float* obs   = (const float*)d_in[0];
    const float* W_emb = (const float*)d_in[1];
    const float* b_emb = (const float*)d_in[2];
    const float* Wih_e = (const float*)d_in[3];
    const float* Whh_e = (const float*)d_in[4];
    const float* bih_e = (const float*)d_in[5];
    const float* bhh_e = (const float*)d_in[6];
    const float* Wih_d = (const float*)d_in[7];
    const float* Whh_d = (const float*)d_in[8];
    const float* bih_d = (const float*)d_in[9];
    const float* bhh_d = (const float*)d_in[10];
    const float* W_fc  = (const float*)d_in[11];
    const float* b_fc  = (const float*)d_in[12];
    float* out = (float*)d_out;

    int B = in_sizes[0] / (OBS_ * 2);
    int pred_len = out_size / (B * 2);

    cudaFuncSetAttribute(vanilla_lstm_kernel,
                         cudaFuncAttributeMaxDynamicSharedMemorySize, SMEM_BYTES);

    int grid = B / MB;   // 512
    vanilla_lstm_kernel<<<grid, NT, SMEM_BYTES>>>(
        obs, W_emb, b_emb, Wih_e, Whh_e, bih_e, bhh_e,
        Wih_d, Whh_d, bih_d, bhh_d, W_fc, b_fc, out, pred_len);
}

// round 17
// speedup vs baseline: 1.0159x; 1.0159x over previous
#include <cuda_runtime.h>
#include <math.h>
#include <cstdint>

#define GATES 256
#define OBS_  20
#define MB    64     // batch per CTA
#define NT    512    // 16 warps = 8 pairs
#define NPAIR 8

typedef unsigned long long ULL;

// ---- SMEM layout (floats) ----
#define OFF_W    0                       // [128][256] swizzled (proven layout)
#define OFF_BIAS (OFF_W + 128*256)       // [256] permuted
#define OFF_WE   (OFF_BIAS + 256)        // [2][64]
#define OFF_BE   (OFF_WE + 128)          // [64]
#define OFF_WFC  (OFF_BE + 64)           // [2][64]
#define OFF_BFC  (OFF_WFC + 128)         // [2]+pad
#define OFF_X    (OFF_BFC + 4)           // NPAIR * [64 rows][8 cols]
#define OFF_H    (OFF_X + NPAIR*512)
#define OFF_OBS  (OFF_H + NPAIR*512)     // NPAIR * [40][8]
#define OFF_EXC  (OFF_OBS + NPAIR*320)   // NPAIR * 2 * 512 (gate exchange)
#define SMEM_FLOATS (OFF_EXC + NPAIR*1024)
#define SMEM_BYTES  (SMEM_FLOATS * 4)

#define FMA_F32X2(d, a, b, c_) \
    asm("fma.rn.f32x2 %0, %1, %2, %3;" : "=l"(d) : "l"(a), "l"(b), "l"(c_))
#define PACK_DUP(out, v) \
    asm("mov.b64 %0, {%1, %1};" : "=l"(out) : "r"(v))
#define UNPACK2(lo, hi, in) \
    asm("mov.b64 {%0, %1}, %2;" : "=r"(lo), "=r"(hi) : "l"(in))
#define BARP(id) asm volatile("bar.sync %0, 64;" :: "r"(id) : "memory")

__device__ __forceinline__ float sigf(float x) {
    return __fdividef(1.0f, 1.0f + __expf(-x));
}
__device__ __forceinline__ float tanh_(float x) {
    float a = fabsf(x);
    float e = __expf(2.0f * a);
    float t = 1.0f - __fdividef(2.0f, e + 1.0f);
    return copysignf(t, x);
}

__global__ void __launch_bounds__(NT, 1)
vanilla_lstm_kernel(const float* __restrict__ obs,
                    const float* __restrict__ W_emb,  const float* __restrict__ b_emb,
                    const float* __restrict__ Wih_e,  const float* __restrict__ Whh_e,
                    const float* __restrict__ bih_e,  const float* __restrict__ bhh_e,
                    const float* __restrict__ Wih_d,  const float* __restrict__ Whh_d,
                    const float* __restrict__ bih_d,  const float* __restrict__ bhh_d,
                    const float* __restrict__ W_fc,   const float* __restrict__ b_fc,
                    float* __restrict__ out, int pred_len)
{
    extern __shared__ float sm[];
    float* sW    = sm + OFF_W;
    float* sBias = sm + OFF_BIAS;
    float* sWe   = sm + OFF_WE;
    float* sBe   = sm + OFF_BE;
    float* sWfc  = sm + OFF_WFC;
    float* sBfc  = sm + OFF_BFC;

    const int tid  = threadIdx.x;
    const int lane = tid & 31;
    const int w    = tid >> 5;
    const int pair = w >> 1;
    const int gp   = w & 1;        // 0: gates i,f ; 1: gates g,o ; also col-half
    const int b0   = blockIdx.x * MB;
    const int barid = 1 + pair;

    // per-pair shared strips
    float4* xP = (float4*)(sm + OFF_X) + pair * 128;   // [64 rows][2 float4]
    float4* hP = (float4*)(sm + OFF_H) + pair * 128;
    float*  oP = sm + OFF_OBS + pair * 320;            // [40][8]
    float*  excS = sm + OFF_EXC + pair * 1024 + gp * 512;
    float*  excL = sm + OFF_EXC + pair * 1024 + (1 - gp) * 512;

    // ---- stage small params ----
    if (tid < 128) sWe[tid] = W_emb[(tid & 63) * 2 + (tid >> 6)];
    if (tid < 64)  sBe[tid] = b_emb[tid];
    if (tid < 128) sWfc[tid] = W_fc[tid];
    if (tid < 2)   sBfc[tid] = b_fc[tid];

    // obs: strip[pair][r][c], c = b & 7
    for (int i = tid; i < MB * 40; i += NT) {
        int b = i / 40, r = i % 40;
        sm[OFF_OBS + (b >> 3) * 320 + r * 8 + (b & 7)] =
            obs[(size_t)(b0 + b) * 40 + r];
    }
    // zero h strips
    for (int i = tid; i < NPAIR * 512; i += NT) sm[OFF_H + i] = 0.0f;

    // ---- weight staging (proven swizzled layout) ----
    auto stageW = [&](const float* Wih, const float* Whh,
                      const float* bih, const float* bhh) {
        for (int i = tid; i < GATES * 64; i += NT) {
            int row = i >> 6, k = i & 63;
            int g = row >> 6, rem = row & 63;
            int l = rem >> 1, d = rem & 1;
            int sz = (l >> 2) & 1;
            int phys = (2 * l + ((g >> 1) ^ sz)) * 4 + (g & 1) * 2 + d;
            sW[k * GATES + phys]        = Wih[i];
            sW[(64 + k) * GATES + phys] = Whh[i];
        }
        for (int row = tid; row < GATES; row += NT) {
            int g = row >> 6, rem = row & 63;
            sBias[(rem >> 1) * 8 + g * 2 + (rem & 1)] = bih[row] + bhh[row];
        }
    };
    stageW(Wih_e, Whh_e, bih_e, bhh_e);
    __syncthreads();

    // ---- per-lane constants ----
    const int swz = (lane >> 2) & 1;
    const char* wx = (const char*)sW + (2 * lane + (gp ^ swz)) * 16;  // own gate pair
    const char* wh = wx + 64 * 1024;

    const int e0 = 2 * lane, e1 = 2 * lane + 1;
    float we00 = sWe[e0], we01 = sWe[64 + e0], be0 = sBe[e0];
    float we10 = sWe[e1], we11 = sWe[64 + e1], be1 = sBe[e1];
    float wfc00 = sWfc[e0], wfc01 = sWfc[e1];
    float wfc10 = sWfc[64 + e0], wfc11 = sWfc[64 + e1];
    float bfc0 = sBfc[0], bfc1 = sBfc[1];

    ULL biasv[2];
    #pragma unroll
    for (int q = 0; q < 2; q++)
        biasv[q] = *(const ULL*)(sBias + lane * 8 + (2 * gp + q) * 2);

    // ---- embed own 4 cols into x strip ----
    auto embed_store = [&](const float* p0, const float* p1) {
        float va[4], vb[4];
        #pragma unroll
        for (int j = 0; j < 4; j++) {
            va[j] = fmaxf(fmaf(p0[j], we00, fmaf(p1[j], we01, be0)), 0.f);
            vb[j] = fmaxf(fmaf(p0[j], we10, fmaf(p1[j], we11, be1)), 0.f);
        }
        xP[4 * lane + gp]     = make_float4(va[0], va[1], va[2], va[3]);
        xP[4 * lane + 2 + gp] = make_float4(vb[0], vb[1], vb[2], vb[3]);
    };
    auto embed_obs_store = [&](int tt) {
        float4 P0 = *(const float4*)(oP + (2 * tt) * 8 + gp * 4);
        float4 P1 = *(const float4*)(oP + (2 * tt + 1) * 8 + gp * 4);
        float p0[4] = {P0.x, P0.y, P0.z, P0.w};
        float p1[4] = {P1.x, P1.y, P1.z, P1.w};
        embed_store(p0, p1);
    };

    // 64-k GEMM for own 2 gates over 8 cols
    auto gemm64 = [&](const float4* src, const char* wp_, ULL a[2][8]) {
        #pragma unroll 4
        for (int k = 0; k < 64; k++) {
            float4 xlo = src[2 * k];
            float4 xhi = src[2 * k + 1];
            ULL xq[8];
            PACK_DUP(xq[0], __float_as_uint(xlo.x));
            PACK_DUP(xq[1], __float_as_uint(xlo.y));
            PACK_DUP(xq[2], __float_as_uint(xlo.z));
            PACK_DUP(xq[3], __float_as_uint(xlo.w));
            PACK_DUP(xq[4], __float_as_uint(xhi.x));
            PACK_DUP(xq[5], __float_as_uint(xhi.y));
            PACK_DUP(xq[6], __float_as_uint(xhi.z));
            PACK_DUP(xq[7], __float_as_uint(xhi.w));
            float4 wv = *(const float4*)(wp_ + k * 1024);
            ULL wq0 = *(ULL*)&wv.x, wq1 = *(ULL*)&wv.z;
            #pragma unroll
            for (int b = 0; b < 8; b++) {
                FMA_F32X2(a[0][b], wq0, xq[b], a[0][b]);
                FMA_F32X2(a[1][b], wq1, xq[b], a[1][b]);
            }
        }
    };

    float c[2][4];     // cell state, own 4 cols
    #pragma unroll
    for (int d = 0; d < 2; d++)
        #pragma unroll
        for (int j = 0; j < 4; j++) c[d][j] = 0.0f;

    const int fb = 4 - gp * 4;   // foreign col base
    const int ob = gp * 4;       // own col base

    const int TOT = OBS_ + pred_len;
    for (int t = 0; t < TOT; t++) {
        if (t == OBS_) {
            __syncthreads();
            stageW(Wih_d, Whh_d, bih_d, bhh_d);
            __syncthreads();
            #pragma unroll
            for (int q = 0; q < 2; q++)
                biasv[q] = *(const ULL*)(sBias + lane * 8 + (2 * gp + q) * 2);
        }
        if (t < OBS_) embed_obs_store(t);
        BARP(barid);                  // x (and prev h) visible to the pair

        ULL acc[2][8];
        #pragma unroll
        for (int q = 0; q < 2; q++)
            #pragma unroll
            for (int b = 0; b < 8; b++) acc[q][b] = biasv[q];

        gemm64(xP, wx, acc);
        if (t > 0) gemm64(hP, wh, acc);

        // activate own gates for all 8 cols.
        // gp=0: q0=i(sig), q1=f(sig);  gp=1: q0=g(tanh), q1=o(sig)
        float act[2][2][8];           // [q][d][col]
        #pragma unroll
        for (int b = 0; b < 8; b++) {
            unsigned lo, hi;
            UNPACK2(lo, hi, acc[0][b]);
            if (gp == 0) {
                act[0][0][b] = sigf(__uint_as_float(lo));
                act[0][1][b] = sigf(__uint_as_float(hi));
            } else {
                act[0][0][b] = tanh_(__uint_as_float(lo));
                act[0][1][b] = tanh_(__uint_as_float(hi));
            }
            UNPACK2(lo, hi, acc[1][b]);
            act[1][0][b] = sigf(__uint_as_float(lo));
            act[1][1][b] = sigf(__uint_as_float(hi));
        }

        // hand foreign cols' gate values to partner
        #pragma unroll
        for (int q = 0; q < 2; q++)
            #pragma unroll
            for (int d = 0; d < 2; d++)
                #pragma unroll
                for (int j = 0; j < 4; j++)
                    excS[((q * 2 + d) * 4 + j) * 32 + lane] = act[q][d][fb + j];
        BARP(barid);

        float pact[2][2][4];
        #pragma unroll
        for (int q = 0; q < 2; q++)
            #pragma unroll
            for (int d = 0; d < 2; d++)
                #pragma unroll
                for (int j = 0; j < 4; j++)
                    pact[q][d][j] = excL[((q * 2 + d) * 4 + j) * 32 + lane];

        // epilogue for own cols
        float hvv[2][4];
        #pragma unroll
        for (int d = 0; d < 2; d++)
            #pragma unroll
            for (int j = 0; j < 4; j++) {
                float si, sf, tg, so;
                if (gp == 0) {
                    si = act[0][d][ob + j]; sf = act[1][d][ob + j];
                    tg = pact[0][d][j];     so = pact[1][d][j];
                } else {
                    si = pact[0][d][j];     sf = pact[1][d][j];
                    tg = act[0][d][ob + j]; so = act[1][d][ob + j];
                }
                float cn = fmaf(sf, c[d][j], si * tg);
                c[d][j] = cn;
                hvv[d][j] = so * tanh_(cn);
            }

        hP[4 * lane + gp]     = make_float4(hvv[0][0], hvv[0][1], hvv[0][2], hvv[0][3]);
        hP[4 * lane + 2 + gp] = make_float4(hvv[1][0], hvv[1][1], hvv[1][2], hvv[1][3]);

        if (t >= OBS_) {
            // FC over own 4 cols: butterfly reduce 8 values
            float r[8];
            #pragma unroll
            for (int j = 0; j < 4; j++) {
                r[j]     = fmaf(hvv[0][j], wfc00, hvv[1][j] * wfc01);
                r[4 + j] = fmaf(hvv[0][j], wfc10, hvv[1][j] * wfc11);
            }
            #pragma unroll
            for (int off = 16; off >= 1; off >>= 1)
                #pragma unroll
                for (int j = 0; j < 8; j++)
                    r[j] += __shfl_xor_sync(0xffffffffu, r[j], off);
            float p0[4], p1[4];
            #pragma unroll
            for (int j = 0; j < 4; j++) { p0[j] = r[j] + bfc0; p1[j] = r[4 + j] + bfc1; }

            if (lane < 4) {
                float o0v = 0.f, o1v = 0.f;
                #pragma unroll
                for (int j = 0; j < 4; j++)
                    if (lane == j) { o0v = p0[j]; o1v = p1[j]; }
                size_t o = ((size_t)(b0 + pair * 8 + ob + lane) * pred_len + (t - OBS_)) * 2;
                *(float2*)(out + o) = make_float2(o0v, o1v);
            }
            if (t < TOT - 1) embed_store(p0, p1);   // x_{t+1}
        }
        // next iteration's first BARP publishes h (and decoder x) to the pair
    }
}

extern "C" void kernel_launch(void* const* d_in, const int* in_sizes, int n_in,
                              void* d_out, int out_size)
{
    const float* obs   = (const float*)d_in[0];
    const float* W_emb = (const float*)d_in[1];
    const float* b_emb = (const float*)d_in[2];
    const float* Wih_e = (const float*)d_in[3];
    const float* Whh_e = (const float*)d_in[4];
    const float* bih_e = (const float*)d_in[5];
    const float* bhh_e = (const float*)d_in[6];
    const float* Wih_d = (const float*)d_in[7];
    const float* Whh_d = (const float*)d_in[8];
    const float* bih_d = (const float*)d_in[9];
    const float* bhh_d = (const float*)d_in[10];
    const float* W_fc  = (const float*)d_in[11];
    const float* b_fc  = (const float*)d_in[12];
    float* out = (float*)d_out;

    int B = in_sizes[0] / (OBS_ * 2);
    int pred_len = out_size / (B * 2);

    cudaFuncSetAttribute(vanilla_lstm_kernel,
                         cudaFuncAttributeMaxDynamicSharedMemorySize, SMEM_BYTES);

    int grid = B / MB;   // 1024
    vanilla_lstm_kernel<<<grid, NT, SMEM_BYTES>>>(
        obs, W_emb, b_emb, Wih_e, Whh_e, bih_e, bhh_e,
        Wih_d, Whh_d, bih_d, bhh_d, W_fc, b_fc, out, pred_len);
}